// round 10
// baseline (speedup 1.0000x reference)
#include <cuda_runtime.h>
#include <math.h>
#include <stdint.h>

// Problem constants (fixed shapes)
#define TOK   32      // only channel n=0 of each batch survives the final slice
#define LSEQ  1024
#define CCH   34
#define DDIM  256
#define NEXP  8
#define PTCH  4       // only first 4 patches survive flat[:, :1024]
#define PLEN  16
#define PRED  96
#define GRID  256
#define NTHR  256

// Scratch (device globals — no allocation allowed)
__device__ float  g_stats[TOK * 2];                // mean, std per token
__device__ float2 g_part[TOK * 8];                 // per-eighth (sum, sumsq)
__device__ float  g_row64[TOK * 64];               // first 64 raw samples per token
__device__ float  g_xp[TOK * PTCH * DDIM];         // 128 x 256
__device__ float  g_gates[TOK * PTCH * NEXP];      // 128 x 8
__device__ float  g_epart[NEXP][TOK * PTCH][DDIM]; // per-expert gated partials (1 MB)
__device__ unsigned g_cnt[3];                      // barrier arrive counters
__device__ unsigned g_gen[3];                      // barrier generations (monotonic)

// ---------------------------------------------------------------------------
// Grid barrier: all GRID CTAs co-resident (grid 256, occ 2 -> 296 slots).
// Tight L2 spin; counter self-resets; generation monotonic across replays.
// ---------------------------------------------------------------------------
__device__ __forceinline__ void grid_barrier(int k)
{
    __syncthreads();
    __threadfence();                       // publish prior writes
    if (threadIdx.x == 0) {
        volatile unsigned* genp = &g_gen[k];
        const unsigned g = *genp;
        const unsigned arrived = atomicAdd(&g_cnt[k], 1u) + 1u;
        if (arrived == GRID) {
            g_cnt[k] = 0;
            __threadfence();
            atomicAdd(&g_gen[k], 1u);      // release
        } else {
            while (*genp == g) {}
        }
        __threadfence();                   // acquire
    }
    __syncthreads();
}

__device__ __forceinline__ void ffma2(unsigned long long& acc,
                                      unsigned long long a,
                                      unsigned long long b)
{
    asm("fma.rn.f32x2 %0, %1, %2, %0;" : "+l"(acc) : "l"(a), "l"(b));
}

// Shared memory, phase-overlaid (max 39.2 KB -> 2 CTAs/SM = 78.4 KB, fits)
struct SmemAB {
    float2 wsum[4];
    float  xps[DDIM];      // xp for this tp row
    float  lgs[NEXP];
    float  xn[PLEN];
    float  mean, stdv;
};
struct SmemC { float xp[128][68]; float w[16][68]; };  // stride 68: conflict-free 16B LDS
struct SmemD { float comb[LSEQ]; };

__global__ void __launch_bounds__(NTHR, 2)
fused_kernel(const float* __restrict__ x,
             const float* __restrict__ Wp, const float* __restrict__ bp,
             const float* __restrict__ Wr, const float* __restrict__ br,
             const float* __restrict__ We, const float* __restrict__ be,
             const float* __restrict__ Wh, const float* __restrict__ bh,
             float* __restrict__ out)
{
    __shared__ union { SmemAB ab; SmemC c; SmemD d; } sm;

    const int bid = blockIdx.x;
    const int tid = threadIdx.x, lane = tid & 31, warp = tid >> 5;

    // ---- L2 prefetch of ALL later-phase weights (overlaps phase A) --------
    {
        // We: 2MB / 256 CTAs = 64 lines of 128B each
        const char* wp = (const char*)(We + (size_t)bid * 2048);
        if (tid < 64)
            asm volatile("prefetch.global.L2 [%0];" :: "l"(wp + tid * 128));
        // Wh: 384KB / 256 CTAs = 12 lines
        const char* hp = (const char*)(Wh + (size_t)bid * 384);
        if (tid >= 64 && tid < 76)
            asm volatile("prefetch.global.L2 [%0];" :: "l"(hp + (tid - 64) * 128));
        if (tid == 96) {
            if (bid < 128)   // Wp: 16KB
                asm volatile("prefetch.global.L2 [%0];" :: "l"((const char*)Wp + bid * 128));
            if (bid < 64) {  // Wr: 8KB, be: 8KB
                asm volatile("prefetch.global.L2 [%0];" :: "l"((const char*)Wr + bid * 128));
                asm volatile("prefetch.global.L2 [%0];" :: "l"((const char*)be + bid * 128));
            }
            if (bid < 8)     // bp: 1KB
                asm volatile("prefetch.global.L2 [%0];" :: "l"((const char*)bp + bid * 128));
            if (bid < 3)     // bh: 384B
                asm volatile("prefetch.global.L2 [%0];" :: "l"((const char*)bh + bid * 128));
        }
    }

    // ============ Phase A: gather eighth-row + partial stats ================
    // CTA = (token b, eighth o). 128 elements per CTA -> max chip-wide MLP.
    {
        const int b = bid >> 3, o = bid & 7;
        if (tid < 128) {
            const float v = x[((size_t)(b * LSEQ + o * 128 + tid)) * CCH + 2];
            if (o == 0 && tid < 64) g_row64[b * 64 + tid] = v;

            float s = v, s2 = v * v;
            #pragma unroll
            for (int of = 16; of > 0; of >>= 1) {
                s  += __shfl_down_sync(0xffffffffu, s,  of);
                s2 += __shfl_down_sync(0xffffffffu, s2, of);
            }
            if (lane == 0) sm.ab.wsum[warp] = make_float2(s, s2);
        }
        __syncthreads();
        if (tid == 0) {
            float a = 0.f, a2 = 0.f;
            #pragma unroll
            for (int w = 0; w < 4; w++) { a += sm.ab.wsum[w].x; a2 += sm.ab.wsum[w].y; }
            g_part[b * 8 + o] = make_float2(a, a2);
        }
    }

    grid_barrier(0);

    // ===== Phase B: stats finalize + xp + router gates (128 CTAs) ==========
    if (bid < TOK * PTCH) {
        const int b = bid >> 2, p = bid & 3;
        const int tp = b * PTCH + p;

        if (tid == 0) {
            float s = 0.f, s2 = 0.f;
            #pragma unroll
            for (int q = 0; q < 8; q++) { float2 pp = g_part[b * 8 + q]; s += pp.x; s2 += pp.y; }
            const float mean = s * (1.f / LSEQ);
            const float var  = s2 * (1.f / LSEQ) - mean * mean;
            const float stdv = sqrtf(var + 1e-5f);
            sm.ab.mean = mean; sm.ab.stdv = stdv;
            if (p == 0) { g_stats[b * 2] = mean; g_stats[b * 2 + 1] = stdv; }
        }
        __syncthreads();
        const float mean = sm.ab.mean, inv_std = 1.f / sm.ab.stdv;

        if (tid < PLEN)
            sm.ab.xn[tid] = (g_row64[b * 64 + p * PLEN + tid] - mean) * inv_std;
        __syncthreads();

        // xp[j] = xn . Wp[j] + bp[j], thread = j
        {
            const int j = tid;
            float wreg[PLEN];
            #pragma unroll
            for (int k = 0; k < PLEN; k++) wreg[k] = Wp[j * PLEN + k];
            float a = bp[j];
            #pragma unroll
            for (int k = 0; k < PLEN; k++) a += sm.ab.xn[k] * wreg[k];
            sm.ab.xps[j] = a;
            g_xp[tp * DDIM + j] = a;
        }
        __syncthreads();

        // router logits: warp e, shuffle reduce over 256 elements
        {
            const int e = warp;
            const float* wr = Wr + e * DDIM + lane * 8;
            const float4 w0 = *(const float4*)wr;
            const float4 w1 = *(const float4*)(wr + 4);
            const float4 x0 = *(const float4*)&sm.ab.xps[lane * 8];
            const float4 x1 = *(const float4*)&sm.ab.xps[lane * 8 + 4];
            float lg = w0.x * x0.x + w0.y * x0.y + w0.z * x0.z + w0.w * x0.w
                     + w1.x * x1.x + w1.y * x1.y + w1.z * x1.z + w1.w * x1.w;
            #pragma unroll
            for (int o = 16; o > 0; o >>= 1) lg += __shfl_xor_sync(0xffffffffu, lg, o);
            if (lane == 0) sm.ab.lgs[e] = lg + br[e];
        }
        __syncthreads();

        // softmax -> gates
        if (tid == 0) {
            float mx = -1e30f;
            #pragma unroll
            for (int e = 0; e < NEXP; e++) mx = fmaxf(mx, sm.ab.lgs[e]);
            float ex[NEXP]; float smm = 0.f;
            #pragma unroll
            for (int e = 0; e < NEXP; e++) { ex[e] = expf(sm.ab.lgs[e] - mx); smm += ex[e]; }
            const float inv = 1.f / smm;
            #pragma unroll
            for (int e = 0; e < NEXP; e++) g_gates[tp * NEXP + e] = ex[e] * inv;
        }
    }

    grid_barrier(1);

    // ====== Phase C: gated expert GEMM (128 CTAs; crossbar-optimal tiling) ==
    if (bid < 128) {
        const int e  = bid >> 4;
        const int h0 = (bid & 15) * 16;
        const int row_base = (warp >> 2) * 64;   // 0 or 64
        const int hl = (warp & 3) * 4;           // local h base: 0,4,8,12

        unsigned long long acc[2][4];
        #pragma unroll
        for (int q = 0; q < 2; q++)
            #pragma unroll
            for (int j = 0; j < 4; j++) acc[q][j] = 0ull;

        const float* Wbase = We + ((size_t)e * DDIM + h0) * DDIM;

        for (int kt = 0; kt < 4; kt++) {
            const int k0 = kt * 64;
            #pragma unroll
            for (int i = 0; i < 8; i++) {
                const int idx = tid + i * 256;
                const int r = idx >> 4, c = (idx & 15) * 4;
                *(float4*)&sm.c.xp[r][c] = *(const float4*)&g_xp[r * DDIM + k0 + c];
            }
            {
                const int r = tid >> 4, c = (tid & 15) * 4;
                *(float4*)&sm.c.w[r][c] = *(const float4*)&Wbase[r * DDIM + k0 + c];
            }
            __syncthreads();

            #pragma unroll
            for (int kk = 0; kk < 64; kk += 4) {
                ulonglong2 xv[2];
                #pragma unroll
                for (int q = 0; q < 2; q++)
                    xv[q] = *(const ulonglong2*)&sm.c.xp[row_base + q * 32 + lane][kk];
                #pragma unroll
                for (int j = 0; j < 4; j++) {
                    const ulonglong2 wv = *(const ulonglong2*)&sm.c.w[hl + j][kk];
                    #pragma unroll
                    for (int q = 0; q < 2; q++) {
                        ffma2(acc[q][j], xv[q].x, wv.x);
                        ffma2(acc[q][j], xv[q].y, wv.y);
                    }
                }
            }
            __syncthreads();
        }

        #pragma unroll
        for (int q = 0; q < 2; q++) {
            const int tp = row_base + q * 32 + lane;
            const float g = g_gates[tp * NEXP + e];
            #pragma unroll
            for (int j = 0; j < 4; j++) {
                const int h = h0 + hl + j;
                const float2 f = *(const float2*)&acc[q][j];
                g_epart[e][tp][h] = g * (f.x + f.y + be[e * DDIM + h]);
            }
        }
    }

    grid_barrier(2);

    // ===== Phase D: e-reduce with denorm folded + head GEMV (256 CTAs) =====
    {
        const int b = bid >> 3, oct = bid & 7;
        const float mean = g_stats[b * 2], stdv = g_stats[b * 2 + 1];

        // comb'[i] = stdv * sum_e epart[e][...] + mean  (denorm folded here,
        // so the GEMV needs only ONE reduction value per output row)
        {
            const int i0 = tid * 4;
            const int p = i0 >> 8, h = i0 & 255;
            float4 sum = make_float4(0.f, 0.f, 0.f, 0.f);
            #pragma unroll
            for (int e = 0; e < NEXP; e++) {
                const float4 v = *(const float4*)&g_epart[e][b * 4 + p][h];
                sum.x += v.x; sum.y += v.y; sum.z += v.z; sum.w += v.w;
            }
            sum.x = stdv * sum.x + mean;
            sum.y = stdv * sum.y + mean;
            sum.z = stdv * sum.z + mean;
            sum.w = stdv * sum.w + mean;
            *(float4*)&sm.d.comb[i0] = sum;
        }
        __syncthreads();

        // out[b][t] = <comb', Wh[t]> + bh[t]; 12 rows per CTA, <=2 per warp
        #pragma unroll
        for (int rr = 0; rr < 2; rr++) {
            const int r = warp + rr * 8;
            if (r < 12) {
                const int t = oct * 12 + r;
                const float* wrow = Wh + (size_t)t * LSEQ;
                float acc = 0.f;
                #pragma unroll
                for (int i = 0; i < 8; i++) {
                    const float4 w  = *(const float4*)&wrow[lane * 4 + i * 128];
                    const float4 cv = *(const float4*)&sm.d.comb[lane * 4 + i * 128];
                    acc += w.x * cv.x + w.y * cv.y + w.z * cv.z + w.w * cv.w;
                }
                #pragma unroll
                for (int o = 16; o > 0; o >>= 1)
                    acc += __shfl_xor_sync(0xffffffffu, acc, o);
                if (lane == 0) out[b * PRED + t] = acc + bh[t];
            }
        }
    }
}

// ---------------------------------------------------------------------------
extern "C" void kernel_launch(void* const* d_in, const int* in_sizes, int n_in,
                              void* d_out, int out_size)
{
    const float* x  = (const float*)d_in[0];
    // d_in[1..3]: x_mark_enc, x_dec, x_mark_dec — unused by the reference math
    const float* Wp = (const float*)d_in[4];
    const float* bp = (const float*)d_in[5];
    const float* Wr = (const float*)d_in[6];
    const float* br = (const float*)d_in[7];
    const float* We = (const float*)d_in[8];
    const float* be = (const float*)d_in[9];
    const float* Wh = (const float*)d_in[10];
    const float* bh = (const float*)d_in[11];
    float* out = (float*)d_out;

    fused_kernel<<<GRID, NTHR>>>(x, Wp, bp, Wr, br, We, be, Wh, bh, out);
}

// round 14
// speedup vs baseline: 1.2058x; 1.2058x over previous
#include <cuda_runtime.h>
#include <math.h>
#include <stdint.h>

// Problem constants (fixed shapes)
#define TOK   32      // only channel n=0 of each batch survives the final slice
#define LSEQ  1024
#define CCH   34
#define DDIM  256
#define NEXP  8
#define PTCH  4       // only first 4 patches survive flat[:, :1024]
#define PLEN  16
#define PRED  96
#define GRID  128
#define NTHR  256
#define CLUSTER 4

// Scratch (device globals — no allocation allowed)
__device__ float  g_stats[TOK * 2];                // mean, std per token
__device__ float  g_xp[TOK * PTCH * DDIM];         // 128 x 256
__device__ float  g_gates[TOK * PTCH * NEXP];      // 128 x 8
__device__ float  g_epart[NEXP][TOK * PTCH][DDIM]; // per-expert gated partials (1 MB)
__device__ unsigned g_cnt[2];                      // barrier arrive counters
__device__ unsigned g_gen[2];                      // barrier generations (monotonic)

// ---------------------------------------------------------------------------
// Cluster / DSMEM helpers
// ---------------------------------------------------------------------------
__device__ __forceinline__ uint32_t smem_cvt(const void* p) {
    uint32_t a;
    asm("{ .reg .u64 t; cvta.to.shared.u64 t, %1; cvt.u32.u64 %0, t; }"
        : "=r"(a) : "l"(p));
    return a;
}
__device__ __forceinline__ uint32_t mapa_u32(uint32_t a, uint32_t rank) {
    uint32_t r;
    asm("mapa.shared::cluster.u32 %0, %1, %2;" : "=r"(r) : "r"(a), "r"(rank));
    return r;
}
__device__ __forceinline__ void st_cluster_f2(uint32_t addr, float2 v) {
    unsigned long long u = *(unsigned long long*)&v;
    asm volatile("st.shared::cluster.b64 [%0], %1;" :: "r"(addr), "l"(u) : "memory");
}
__device__ __forceinline__ float ld_cluster_f32(uint32_t addr) {
    float v;
    asm volatile("ld.shared::cluster.f32 %0, [%1];" : "=f"(v) : "r"(addr) : "memory");
    return v;
}
#define CLUSTER_SYNC() do { \
    asm volatile("barrier.cluster.arrive.aligned;" ::: "memory"); \
    asm volatile("barrier.cluster.wait.aligned;"   ::: "memory"); \
} while (0)

// ---------------------------------------------------------------------------
// Fence-free grid barrier (CUTLASS-style scoped atomics).
// __syncthreads() gives intra-CTA happens-before; thread 0's release-atomic
// publishes the whole CTA's writes; spinners use ld.acquire with backoff;
// the final __syncthreads() propagates thread 0's acquire to the CTA.
// ---------------------------------------------------------------------------
__device__ __forceinline__ unsigned atom_add_acqrel(unsigned* p) {
    unsigned old;
    asm volatile("atom.add.acq_rel.gpu.u32 %0, [%1], 1;"
                 : "=r"(old) : "l"(p) : "memory");
    return old;
}
__device__ __forceinline__ unsigned ld_acquire(unsigned* p) {
    unsigned v;
    asm volatile("ld.acquire.gpu.u32 %0, [%1];" : "=r"(v) : "l"(p) : "memory");
    return v;
}
__device__ __forceinline__ void st_relaxed(unsigned* p, unsigned v) {
    asm volatile("st.relaxed.gpu.u32 [%0], %1;" :: "l"(p), "r"(v) : "memory");
}
__device__ __forceinline__ void red_release(unsigned* p) {
    asm volatile("red.add.release.gpu.u32 [%0], 1;" :: "l"(p) : "memory");
}

__device__ __forceinline__ void grid_barrier(int k)
{
    __syncthreads();
    if (threadIdx.x == 0) {
        const unsigned g0 = ld_acquire(&g_gen[k]);      // pre-arrival generation
        const unsigned arrived = atom_add_acqrel(&g_cnt[k]);
        if (arrived == GRID - 1) {
            st_relaxed(&g_cnt[k], 0);                   // ordered by release below
            red_release(&g_gen[k]);                     // release all spinners
        } else {
            int spins = 0;
            while (ld_acquire(&g_gen[k]) == g0) {
                if (++spins > 64) __nanosleep(64);      // back off: stop hammering L2
            }
        }
    }
    __syncthreads();
}

__device__ __forceinline__ void ffma2(unsigned long long& acc,
                                      unsigned long long a,
                                      unsigned long long b)
{
    asm("fma.rn.f32x2 %0, %1, %2, %0;" : "+l"(acc) : "l"(a), "l"(b));
}

// Shared memory, phase-overlaid (max ~39.2 KB < 48 KB static limit)
struct SmemAB {
    float  row[256];       // this CTA's raw quarter (rank 0's slice read by B)
    float2 part[CLUSTER];  // gathered quarter (sum, sumsq)
    float2 wsum[8];
    float  xps[DDIM];      // xp for this tp row
    float  lgs[NEXP];
    float  xn[PLEN];
    float  mean, stdv;
};
struct SmemC { float xp[128][68]; float w[16][68]; };  // stride 68: conflict-free 16B LDS
struct SmemD { float comb[LSEQ]; };

__global__ void __launch_bounds__(NTHR, 1) __cluster_dims__(CLUSTER, 1, 1)
fused_kernel(const float* __restrict__ x,
             const float* __restrict__ Wp, const float* __restrict__ bp,
             const float* __restrict__ Wr, const float* __restrict__ br,
             const float* __restrict__ We, const float* __restrict__ be,
             const float* __restrict__ Wh, const float* __restrict__ bh,
             float* __restrict__ out)
{
    __shared__ union { SmemAB ab; SmemC c; SmemD d; } sm;

    const int bid = blockIdx.x;
    const int tid = threadIdx.x, lane = tid & 31, warp = tid >> 5;

    // ---- L2 prefetch of ALL later-phase weights (overlaps phase A) --------
    {
        // We: 2MB / 128 CTAs = 128 lines of 128B each
        const char* wp = (const char*)(We + (size_t)bid * 4096);
        if (tid < 128)
            asm volatile("prefetch.global.L2 [%0];" :: "l"(wp + tid * 128));
        // Wh: 384KB / 128 CTAs = 24 lines
        const char* hp = (const char*)(Wh + (size_t)bid * 768);
        if (tid < 24)
            asm volatile("prefetch.global.L2 [%0];" :: "l"(hp + tid * 128));
        if (tid == 64) {
            // Wp: 16KB = 128 lines (one per CTA)
            asm volatile("prefetch.global.L2 [%0];" :: "l"((const char*)Wp + bid * 128));
            if (bid < 64) {  // Wr: 8KB, be: 8KB
                asm volatile("prefetch.global.L2 [%0];" :: "l"((const char*)Wr + bid * 128));
                asm volatile("prefetch.global.L2 [%0];" :: "l"((const char*)be + bid * 128));
            }
            if (bid < 8)     // bp: 1KB
                asm volatile("prefetch.global.L2 [%0];" :: "l"((const char*)bp + bid * 128));
            if (bid < 3)     // bh: 384B
                asm volatile("prefetch.global.L2 [%0];" :: "l"((const char*)bh + bid * 128));
        }
    }

    // ================= Phase A: gather quarter + partial stats =============
    // CTA = (token b, quarter q). Cluster of 4 CTAs = one token.
    {
        const int b = bid >> 2, q = bid & 3;
        const float v = x[((size_t)(b * LSEQ + q * 256 + tid)) * CCH + 2];
        sm.ab.row[tid] = v;

        float s = v, s2 = v * v;
        #pragma unroll
        for (int o = 16; o > 0; o >>= 1) {
            s  += __shfl_down_sync(0xffffffffu, s,  o);
            s2 += __shfl_down_sync(0xffffffffu, s2, o);
        }
        if (lane == 0) sm.ab.wsum[warp] = make_float2(s, s2);
        __syncthreads();
        if (tid == 0) {
            float a = 0.f, a2 = 0.f;
            #pragma unroll
            for (int w = 0; w < 8; w++) { a += sm.ab.wsum[w].x; a2 += sm.ab.wsum[w].y; }
            // scatter this quarter's partial to all 4 cluster CTAs via DSMEM
            const uint32_t la = smem_cvt(&sm.ab.part[q]);
            #pragma unroll
            for (int r = 0; r < CLUSTER; r++)
                st_cluster_f2(mapa_u32(la, r), make_float2(a, a2));
        }
    }
    CLUSTER_SYNC();   // orders DSMEM partials + row[] across the token's 4 CTAs

    // ===== Phase B: stats finalize + xp + router gates (all 128 CTAs) ======
    // CTA = (token b, patch p). p == q from phase A.
    {
        const int b = bid >> 2, p = bid & 3;
        const int tp = b * PTCH + p;

        if (tid == 0) {
            float s = 0.f, s2 = 0.f;
            #pragma unroll
            for (int q = 0; q < CLUSTER; q++) { float2 pp = sm.ab.part[q]; s += pp.x; s2 += pp.y; }
            const float mean = s * (1.f / LSEQ);
            const float var  = s2 * (1.f / LSEQ) - mean * mean;
            const float stdv = sqrtf(var + 1e-5f);
            sm.ab.mean = mean; sm.ab.stdv = stdv;
            if (p == 0) { g_stats[b * 2] = mean; g_stats[b * 2 + 1] = stdv; }
        }
        __syncthreads();
        const float mean = sm.ab.mean, inv_std = 1.f / sm.ab.stdv;

        // normalized patch samples live in rank 0's row[p*16 .. p*16+15]
        if (tid < PLEN) {
            const uint32_t la = smem_cvt(&sm.ab.row[p * PLEN + tid]);
            const float v = ld_cluster_f32(mapa_u32(la, 0));
            sm.ab.xn[tid] = (v - mean) * inv_std;
        }
        __syncthreads();

        // xp[j] = xn . Wp[j] + bp[j], thread = j
        {
            const int j = tid;
            float wreg[PLEN];
            #pragma unroll
            for (int k = 0; k < PLEN; k++) wreg[k] = Wp[j * PLEN + k];
            float a = bp[j];
            #pragma unroll
            for (int k = 0; k < PLEN; k++) a += sm.ab.xn[k] * wreg[k];
            sm.ab.xps[j] = a;
            g_xp[tp * DDIM + j] = a;
        }
        __syncthreads();

        // router logits: warp e, shuffle reduce over 256 elements
        {
            const int e = warp;
            const float* wr = Wr + e * DDIM + lane * 8;
            const float4 w0 = *(const float4*)wr;
            const float4 w1 = *(const float4*)(wr + 4);
            const float4 x0 = *(const float4*)&sm.ab.xps[lane * 8];
            const float4 x1 = *(const float4*)&sm.ab.xps[lane * 8 + 4];
            float lg = w0.x * x0.x + w0.y * x0.y + w0.z * x0.z + w0.w * x0.w
                     + w1.x * x1.x + w1.y * x1.y + w1.z * x1.z + w1.w * x1.w;
            #pragma unroll
            for (int o = 16; o > 0; o >>= 1) lg += __shfl_xor_sync(0xffffffffu, lg, o);
            if (lane == 0) sm.ab.lgs[e] = lg + br[e];
        }
        __syncthreads();

        // softmax -> gates
        if (tid == 0) {
            float mx = -1e30f;
            #pragma unroll
            for (int e = 0; e < NEXP; e++) mx = fmaxf(mx, sm.ab.lgs[e]);
            float ex[NEXP]; float smm = 0.f;
            #pragma unroll
            for (int e = 0; e < NEXP; e++) { ex[e] = expf(sm.ab.lgs[e] - mx); smm += ex[e]; }
            const float inv = 1.f / smm;
            #pragma unroll
            for (int e = 0; e < NEXP; e++) g_gates[tp * NEXP + e] = ex[e] * inv;
        }
    }

    grid_barrier(0);

    // ====== Phase C: gated expert GEMM, register double-buffered ===========
    {
        const int e  = bid >> 4;
        const int h0 = (bid & 15) * 16;
        const int row_base = (warp >> 2) * 64;   // 0 or 64
        const int hl = (warp & 3) * 4;           // local h base: 0,4,8,12

        unsigned long long acc[2][4];
        #pragma unroll
        for (int q = 0; q < 2; q++)
            #pragma unroll
            for (int j = 0; j < 4; j++) acc[q][j] = 0ull;

        const float* Wbase = We + ((size_t)e * DDIM + h0) * DDIM;
        const int ldr = tid >> 4, ldc = (tid & 15) * 4;   // W-stage coords

        // preload k-tile 0 straight into smem
        #pragma unroll
        for (int i = 0; i < 8; i++) {
            const int idx = tid + i * 256;
            const int r = idx >> 4, c = (idx & 15) * 4;
            *(float4*)&sm.c.xp[r][c] = *(const float4*)&g_xp[r * DDIM + c];
        }
        *(float4*)&sm.c.w[ldr][ldc] = *(const float4*)&Wbase[ldr * DDIM + ldc];
        __syncthreads();

        for (int kt = 0; kt < 4; kt++) {
            // issue next tile's global loads into registers (hidden by compute)
            float4 nx[8], nw;
            if (kt < 3) {
                const int k0n = (kt + 1) * 64;
                #pragma unroll
                for (int i = 0; i < 8; i++) {
                    const int idx = tid + i * 256;
                    const int r = idx >> 4, c = (idx & 15) * 4;
                    nx[i] = *(const float4*)&g_xp[r * DDIM + k0n + c];
                }
                nw = *(const float4*)&Wbase[ldr * DDIM + k0n + ldc];
            }

            #pragma unroll
            for (int kk = 0; kk < 64; kk += 4) {
                ulonglong2 xv[2];
                #pragma unroll
                for (int q = 0; q < 2; q++)
                    xv[q] = *(const ulonglong2*)&sm.c.xp[row_base + q * 32 + lane][kk];
                #pragma unroll
                for (int j = 0; j < 4; j++) {
                    const ulonglong2 wv = *(const ulonglong2*)&sm.c.w[hl + j][kk];
                    #pragma unroll
                    for (int q = 0; q < 2; q++) {
                        ffma2(acc[q][j], xv[q].x, wv.x);
                        ffma2(acc[q][j], xv[q].y, wv.y);
                    }
                }
            }
            __syncthreads();

            if (kt < 3) {
                #pragma unroll
                for (int i = 0; i < 8; i++) {
                    const int idx = tid + i * 256;
                    const int r = idx >> 4, c = (idx & 15) * 4;
                    *(float4*)&sm.c.xp[r][c] = nx[i];
                }
                *(float4*)&sm.c.w[ldr][ldc] = nw;
                __syncthreads();
            }
        }

        #pragma unroll
        for (int q = 0; q < 2; q++) {
            const int tp = row_base + q * 32 + lane;
            const float g = g_gates[tp * NEXP + e];
            #pragma unroll
            for (int j = 0; j < 4; j++) {
                const int h = h0 + hl + j;
                const float2 f = *(const float2*)&acc[q][j];
                g_epart[e][tp][h] = g * (f.x + f.y + be[e * DDIM + h]);
            }
        }
    }

    grid_barrier(1);

    // ===== Phase D: e-reduce with denorm folded + head GEMV (128 CTAs) =====
    {
        const int b = bid >> 2, tq = bid & 3;
        const float mean = g_stats[b * 2], stdv = g_stats[b * 2 + 1];

        // comb'[i] = stdv * sum_e epart[e][...] + mean (denorm folded here)
        {
            const int i0 = tid * 4;
            const int p = i0 >> 8, h = i0 & 255;
            float4 sum = make_float4(0.f, 0.f, 0.f, 0.f);
            #pragma unroll
            for (int e = 0; e < NEXP; e++) {
                const float4 v = *(const float4*)&g_epart[e][b * 4 + p][h];
                sum.x += v.x; sum.y += v.y; sum.z += v.z; sum.w += v.w;
            }
            sum.x = stdv * sum.x + mean;
            sum.y = stdv * sum.y + mean;
            sum.z = stdv * sum.z + mean;
            sum.w = stdv * sum.w + mean;
            *(float4*)&sm.d.comb[i0] = sum;
        }
        __syncthreads();

        // out[b][t] = <comb', Wh[t]> + bh[t]; 24 rows per CTA, 3 per warp
        #pragma unroll
        for (int r = 0; r < 3; r++) {
            const int t = tq * 24 + warp * 3 + r;
            const float* wrow = Wh + (size_t)t * LSEQ;
            float acc = 0.f;
            #pragma unroll
            for (int i = 0; i < 8; i++) {
                const float4 w  = *(const float4*)&wrow[lane * 4 + i * 128];
                const float4 cv = *(const float4*)&sm.d.comb[lane * 4 + i * 128];
                acc += w.x * cv.x + w.y * cv.y + w.z * cv.z + w.w * cv.w;
            }
            #pragma unroll
            for (int o = 16; o > 0; o >>= 1)
                acc += __shfl_xor_sync(0xffffffffu, acc, o);
            if (lane == 0) out[b * PRED + t] = acc + bh[t];
        }
    }
}

// ---------------------------------------------------------------------------
extern "C" void kernel_launch(void* const* d_in, const int* in_sizes, int n_in,
                              void* d_out, int out_size)
{
    const float* x  = (const float*)d_in[0];
    // d_in[1..3]: x_mark_enc, x_dec, x_mark_dec — unused by the reference math
    const float* Wp = (const float*)d_in[4];
    const float* bp = (const float*)d_in[5];
    const float* Wr = (const float*)d_in[6];
    const float* br = (const float*)d_in[7];
    const float* We = (const float*)d_in[8];
    const float* be = (const float*)d_in[9];
    const float* Wh = (const float*)d_in[10];
    const float* bh = (const float*)d_in[11];
    float* out = (float*)d_out;

    fused_kernel<<<GRID, NTHR>>>(x, Wp, bp, Wr, br, We, be, Wh, bh, out);
}